// round 11
// baseline (speedup 1.0000x reference)
#include <cuda_runtime.h>
#include <cstdint>

#define VOCAB   32000
#define VWORDS  8000          // VOCAB / 4 (float4 words)
#define TPB     512
#define NBINS   2048
#define QCAP    64            // max gathered octets (-> 512 candidates)
#define MCAP    192           // max compact (element-level) candidates

typedef unsigned long long u64;
typedef unsigned int       u32;

__device__ int g_done_ctr = 0;

__device__ __forceinline__ u32 f2s(float f) {
    u32 b = __float_as_uint(f);
    return (b & 0x80000000u) ? ~b : (b | 0x80000000u);
}

__device__ __forceinline__ u32 block_scan_u32(u32 v, u32* smem16, int tid) {
    int lane = tid & 31, wid = tid >> 5;
    u32 x = v;
#pragma unroll
    for (int o = 1; o < 32; o <<= 1) {
        u32 t = __shfl_up_sync(0xffffffffu, x, o);
        if (lane >= o) x += t;
    }
    if (lane == 31) smem16[wid] = x;
    __syncthreads();
    if (wid == 0) {
        u32 w = (lane < 16) ? smem16[lane] : 0u;
#pragma unroll
        for (int o = 1; o < 16; o <<= 1) {
            u32 t = __shfl_up_sync(0xffffffffu, w, o);
            if (lane >= o) w += t;
        }
        if (lane < 16) smem16[lane] = w;
    }
    __syncthreads();
    return x + (wid ? smem16[wid - 1] : 0u);
}

// branchless descending top-6 insert; alternate int/float minmax pipes.
__device__ __forceinline__ void ins6(u32 k, u32 (&tv)[6]) {
#pragma unroll
    for (int q = 0; q < 6; q++) {
        if (q & 1) {
            float a = __uint_as_float(tv[q]), b = __uint_as_float(k);
            float hi = fmaxf(a, b), lo = fminf(a, b);
            tv[q] = __float_as_uint(hi); k = __float_as_uint(lo);
        } else {
            u32 hi = max(tv[q], k), lo = min(tv[q], k);
            tv[q] = hi; k = lo;
        }
    }
}

__device__ __forceinline__ float ex2f(float y) {
    float r;
    asm("ex2.approx.f32 %0, %1;" : "=f"(r) : "f"(y));
    return r;
}

// 4 elements: Z accumulate, return max exp
__device__ __forceinline__ float half4(float4 v, float c1,
                                       float& z0, float& z1, float& z2, float& z3) {
    float e0 = ex2f(v.x * c1), e1 = ex2f(v.y * c1);
    float e2 = ex2f(v.z * c1), e3 = ex2f(v.w * c1);
    z0 += e0; z1 += e1; z2 += e2; z3 += e3;
    return fmaxf(fmaxf(e0, e1), fmaxf(e2, e3));
}

// guarded variant for the tail stage (never trusts stale smem)
__device__ __forceinline__ float half4g(float4 v, float c1, bool g,
                                        float& z0, float& z1, float& z2, float& z3) {
    float x0 = g ? v.x * c1 : -1e30f;
    float x1 = g ? v.y * c1 : -1e30f;
    float x2 = g ? v.z * c1 : -1e30f;
    float x3 = g ? v.w * c1 : -1e30f;
    float e0 = ex2f(x0), e1 = ex2f(x1), e2 = ex2f(x2), e3 = ex2f(x3);
    z0 += e0; z1 += e1; z2 += e2; z3 += e3;
    return fmaxf(fmaxf(e0, e1), fmaxf(e2, e3));
}

__global__ __launch_bounds__(TPB, 3)
void sampler_row_kernel(const float* __restrict__ logits,
                        const float* __restrict__ gumbel,
                        const float* __restrict__ temp_p,
                        const float* __restrict__ topp_p,
                        const int*   __restrict__ topk_p,
                        const float* __restrict__ thr_p,
                        float* __restrict__ out, int N)
{
    __shared__ float4 s_stage[2][1024];         // 32 KB double buffer
    __shared__ u32    s_hist[NBINS];            // 8 KB (reused for both tiers)
    __shared__ u32    s_g32[QCAP];              // gathered octet keys
    __shared__ u64    s_ckey[MCAP];             // compact candidate keys
    __shared__ float  s_cexp[MCAP];
    __shared__ float  s_cx[MCAP];
    __shared__ int    s_cidx[MCAP];
    __shared__ u32    s_t16[16];
    __shared__ u64    s_red64[16];
    __shared__ float  s_redf[16];
    __shared__ float  s_Z;
    __shared__ int    s_bin, s_gcnt, s_cnt2, s_last;

    const int tid  = threadIdx.x;
    const int row  = blockIdx.x;
    const int wid  = tid >> 5;
    const int lane = tid & 31;

    const float invT = 1.0f / (*temp_p);
    const float c1   = 1.44269504088896341f * invT;   // log2(e)/T
    const float topP = *topp_p;
    int Kw = *topk_p;
    Kw = max(1, min(Kw, 512));
    const int KQ = min(Kw, QCAP);          // octet-rank target
    const int Ke = min(Kw, 128);           // element-rank target (compact tier)

    const float* rowp = logits + (size_t)row * VOCAB;
    const float4* rp  = (const float4*)rowp;

    if (tid == 0) { s_gcnt = 0; s_cnt2 = 0; }
#pragma unroll
    for (int q = 0; q < NBINS / TPB; q++) s_hist[tid + q * TPB] = 0u;

    u32 tv[6];
#pragma unroll
    for (int q = 0; q < 6; q++) tv[q] = 0u;
    float z0 = 0.f, z1 = 0.f, z2 = 0.f, z3 = 0.f;

    const u32 sbase = (u32)__cvta_generic_to_shared(s_stage);

    // issue stage s into buffer b (two 16B copies/thread; stage 7 is partial)
#define ISSUE8(s, b)                                                          \
    do {                                                                      \
        if ((s) < 8) {                                                        \
            int _j1 = (s) * 1024 + tid;                                       \
            u32 _d1 = sbase + (u32)(b) * 16384u + (u32)tid * 16u;             \
            if (_j1 < VWORDS)                                                 \
                asm volatile("cp.async.cg.shared.global [%0], [%1], 16;"      \
                             :: "r"(_d1), "l"(rp + _j1));                     \
            if (_j1 + 512 < VWORDS)                                           \
                asm volatile("cp.async.cg.shared.global [%0], [%1], 16;"      \
                             :: "r"(_d1 + 8192u), "l"(rp + _j1 + 512));       \
        }                                                                     \
        asm volatile("cp.async.commit_group;");                               \
    } while (0)

    ISSUE8(0, 0); ISSUE8(1, 1);

    int bs = 0;
#pragma unroll 1
    for (int s = 0; s < 7; s++) {           // full stages
        asm volatile("cp.async.wait_group 1;");
        const float4* buf = &s_stage[bs][0];
        float4 a = buf[tid];
        float4 c = buf[tid + 512];
        float mA = half4(a, c1, z0, z1, z2, z3);
        float mC = half4(c, c1, z0, z1, z2, z3);
        float m  = fmaxf(mA, mC);
        u32 k = (__float_as_uint(m) & 0xFFFFF000u) | (u32)(s * 512 + tid);
        ins6(k, tv);
        ISSUE8(s + 2, bs);
        bs ^= 1;
    }
    {   // tail stage 7 (words 7168..7999)
        asm volatile("cp.async.wait_group 0;");
        const float4* buf = &s_stage[bs][0];
        bool g1 = tid < (VWORDS - 7 * 1024);          // < 832
        bool g2 = tid < (VWORDS - 7 * 1024 - 512);    // < 320
        float4 a = buf[tid];
        float4 c = buf[tid + 512];
        float mA = half4g(a, c1, g1, z0, z1, z2, z3);
        float mC = half4g(c, c1, g2, z0, z1, z2, z3);
        float m  = fmaxf(mA, mC);
        u32 k = (__float_as_uint(m) & 0xFFFFF000u) | (u32)(7 * 512 + tid);
        ins6(k, tv);
    }

    float zsum = (z0 + z1) + (z2 + z3);

    // ---- block-reduce Z ----
#pragma unroll
    for (int off = 16; off; off >>= 1)
        zsum += __shfl_down_sync(0xffffffffu, zsum, off);
    if (lane == 0) s_redf[wid] = zsum;
    __syncthreads();
    if (tid == 0) {
        float z = 0.0f;
        for (int w = 0; w < 16; w++) z += s_redf[w];
        s_Z = z;
    }

    // ---- tier 1: histogram of octet keys (top 11 bits) ----
#pragma unroll
    for (int q = 0; q < 6; q++)
        atomicAdd(&s_hist[tv[q] >> 21], 1u);
    __syncthreads();

    // suffix scan from highest bin; locate rank-KQ bin
    u32 c4[4]; u32 tsum = 0;
#pragma unroll
    for (int q = 0; q < 4; q++) {
        int bin = (NBINS - 1) - (tid * 4 + q);
        c4[q] = s_hist[bin];
        tsum += c4[q];
    }
    u32 incl = block_scan_u32(tsum, s_t16, tid);
    {
        u32 cum = incl - tsum;
#pragma unroll
        for (int q = 0; q < 4; q++) {
            if (cum < (u32)KQ && cum + c4[q] >= (u32)KQ)
                s_bin = (NBINS - 1) - (tid * 4 + q);
            cum += c4[q];
        }
    }
    __syncthreads();
    const int binSel = s_bin;

    // gather octet keys in bins >= binSel
#pragma unroll
    for (int q = 0; q < 6; q++) {
        u32 key = tv[q];
        if ((int)(key >> 21) >= binSel) {
            int pos = atomicAdd(&s_gcnt, 1);
            if (pos < QCAP) s_g32[pos] = key;
        }
    }
    __syncthreads();
    const int ocnt = min(s_gcnt, QCAP);
    const int gex  = ocnt * 8;           // expanded candidate count

    // ---- tier 2: expand octets in registers; element-level cutoff ----
    u64 myk = 0ull; float mye = 0.0f, myx = 0.0f; int myidx = 0; u32 mybits = 0;
    if (tid < gex) {
        u32 ok = s_g32[tid >> 3];
        int o  = (int)(ok & 0xFFFu);
        int st = o >> 9, tt = o & 511;
        int word = st * 1024 + ((tid >> 2) & 1) * 512 + tt;
        myidx = word * 4 + (tid & 3);
        if (word < VWORDS) {
            myx = __ldg(rowp + myidx) * invT;
            mye = __expf(myx);
            mybits = f2s(myx);
            // tie-break: smaller idx -> larger low word -> higher rank
            myk = (((u64)mybits) << 32) | (u32)(VOCAB - myidx);
        }
    }
    // clear histogram for reuse
#pragma unroll
    for (int q = 0; q < NBINS / TPB; q++) s_hist[tid + q * TPB] = 0u;
    __syncthreads();

    if (tid < gex) atomicAdd(&s_hist[mybits >> 21], 1u);
    __syncthreads();

    // suffix scan; locate element rank-Ke bin
    tsum = 0;
#pragma unroll
    for (int q = 0; q < 4; q++) {
        int bin = (NBINS - 1) - (tid * 4 + q);
        c4[q] = s_hist[bin];
        tsum += c4[q];
    }
    incl = block_scan_u32(tsum, s_t16, tid);
    {
        u32 cum = incl - tsum;
#pragma unroll
        for (int q = 0; q < 4; q++) {
            if (cum < (u32)Ke && cum + c4[q] >= (u32)Ke)
                s_bin = (NBINS - 1) - (tid * 4 + q);
            cum += c4[q];
        }
    }
    __syncthreads();
    const int binSel2 = s_bin;

    // gather compact candidates
    if (tid < gex && (int)(mybits >> 21) >= binSel2) {
        int pos = atomicAdd(&s_cnt2, 1);
        if (pos < MCAP) {
            s_ckey[pos] = myk;
            s_cexp[pos] = mye;
            s_cx[pos]   = myx;
            s_cidx[pos] = myidx;
        }
    }
    __syncthreads();
    const int mcnt = min(s_cnt2, MCAP);

    // ---- all-pairs rank + prefix over compact set ----
    float zc = 0.0f; u64 best = 0ull;
    if (tid < mcnt) {
        u64 mk = s_ckey[tid];
        int R = 0; float S = 0.0f;
        for (int j = 0; j < mcnt; j++) {
            u64 kj = s_ckey[j];
            bool gt = kj > mk;
            R += gt ? 1 : 0;
            S += gt ? s_cexp[j] : 0.0f;
        }
        if (R < Kw && S <= topP * s_Z) {
            zc = s_cexp[tid];
            float g = __ldg(&gumbel[(size_t)row * VOCAB + s_cidx[tid]]);
            best = (((u64)f2s(s_cx[tid] + g)) << 32) | (u32)tid;
        }
    }
#pragma unroll
    for (int off = 16; off; off >>= 1) {
        zc += __shfl_down_sync(0xffffffffu, zc, off);
        u64 o = __shfl_down_sync(0xffffffffu, best, off);
        if (o > best) best = o;
    }
    if (lane == 0) { s_redf[wid] = zc; s_red64[wid] = best; }
    __syncthreads();
    if (tid == 0) {
        float Zp = 0.0f; u64 b = 0ull;
        for (int w = 0; w < 16; w++) {
            Zp += s_redf[w];
            if (s_red64[w] > b) b = s_red64[w];
        }
        int sel = (int)(u32)b;
        float conf = s_cexp[sel] / Zp;
        out[row]         = conf;
        out[N + row]     = (float)s_cidx[sel];
        out[2 * N + row] = conf;

        __threadfence();
        int prev = atomicAdd(&g_done_ctr, 1);
        s_last = (prev == N - 1) ? 1 : 0;
    }
    __syncthreads();

    // ---- last block: cross-row finalize (accepted flags) ----
    if (s_last) {
        __threadfence();
        const float thr = *thr_p;
        u64 fb = 0ull; int anyl = 0;
        float cv[4];
#pragma unroll
        for (int q = 0; q < 4; q++) {
            int r = tid + q * TPB;
            float c = (r < N) ? out[r] : -1.0f;
            cv[q] = c;
            if (r < N) {
                if (c > thr) anyl = 1;
                u64 k = (((u64)f2s(c)) << 32) | (u32)(N - 1 - r);
                if (k > fb) fb = k;
            }
        }
#pragma unroll
        for (int off = 16; off; off >>= 1) {
            u64 o = __shfl_down_sync(0xffffffffu, fb, off);
            if (o > fb) fb = o;
        }
        int anyw = __any_sync(0xffffffffu, anyl);
        if (lane == 0) { s_red64[wid] = fb; s_t16[wid] = (u32)anyw; }
        __syncthreads();
        if (tid == 0) {
            u64 b = 0ull; u32 a = 0;
            for (int w = 0; w < 16; w++) {
                if (s_red64[w] > b) b = s_red64[w];
                a |= s_t16[w];
            }
            s_red64[0] = b;
            s_t16[0] = a;
            g_done_ctr = 0;
        }
        __syncthreads();
        const int argrow = N - 1 - (int)(u32)s_red64[0];
        const int anyh = (int)s_t16[0];
#pragma unroll
        for (int q = 0; q < 4; q++) {
            int r = tid + q * TPB;
            if (r < N)
                out[3 * N + r] = anyh ? ((cv[q] > thr) ? 1.0f : 0.0f)
                                      : ((r == argrow) ? 1.0f : 0.0f);
        }
    }
}

extern "C" void kernel_launch(void* const* d_in, const int* in_sizes, int n_in,
                              void* d_out, int out_size)
{
    const float* logits = (const float*)d_in[0];
    const float* gumbel = (const float*)d_in[1];
    const float* temp   = (const float*)d_in[2];
    const float* topp   = (const float*)d_in[3];
    const int*   topk   = (const int*)  d_in[4];
    const float* thr    = (const float*)d_in[5];

    int N = in_sizes[0] / VOCAB;
    float* out = (float*)d_out;

    sampler_row_kernel<<<N, TPB>>>(logits, gumbel, temp, topp, topk, thr, out, N);
}

// round 12
// speedup vs baseline: 1.0206x; 1.0206x over previous
#include <cuda_runtime.h>
#include <cstdint>

#define VOCAB   32000
#define VWORDS  8000          // VOCAB / 4 (float4 words), < 2^13
#define TPB     512
#define SWORDS  512           // float4 words per stage (8 KB)
#define NSTAGES 16
#define DEPTH   4
#define NBINS   2048
#define QCAP    128           // max gathered quads (-> 512 candidates)
#define MCAP    192           // max compact (element-level) candidates

typedef unsigned long long u64;
typedef unsigned int       u32;

__device__ int g_done_ctr = 0;

__device__ __forceinline__ u32 f2s(float f) {
    u32 b = __float_as_uint(f);
    return (b & 0x80000000u) ? ~b : (b | 0x80000000u);
}

__device__ __forceinline__ u32 block_scan_u32(u32 v, u32* smem16, int tid) {
    int lane = tid & 31, wid = tid >> 5;
    u32 x = v;
#pragma unroll
    for (int o = 1; o < 32; o <<= 1) {
        u32 t = __shfl_up_sync(0xffffffffu, x, o);
        if (lane >= o) x += t;
    }
    if (lane == 31) smem16[wid] = x;
    __syncthreads();
    if (wid == 0) {
        u32 w = (lane < 16) ? smem16[lane] : 0u;
#pragma unroll
        for (int o = 1; o < 16; o <<= 1) {
            u32 t = __shfl_up_sync(0xffffffffu, w, o);
            if (lane >= o) w += t;
        }
        if (lane < 16) smem16[lane] = w;
    }
    __syncthreads();
    return x + (wid ? smem16[wid - 1] : 0u);
}

// branchless descending top-5 insert; alternate int/float minmax pipes.
__device__ __forceinline__ void ins5(u32 k, u32 (&tv)[5]) {
#pragma unroll
    for (int q = 0; q < 5; q++) {
        if (q & 1) {
            float a = __uint_as_float(tv[q]), b = __uint_as_float(k);
            float hi = fmaxf(a, b), lo = fminf(a, b);
            tv[q] = __float_as_uint(hi); k = __float_as_uint(lo);
        } else {
            u32 hi = max(tv[q], k), lo = min(tv[q], k);
            tv[q] = hi; k = lo;
        }
    }
}

__device__ __forceinline__ float ex2f(float y) {
    float r;
    asm("ex2.approx.f32 %0, %1;" : "=f"(r) : "f"(y));
    return r;
}

// 4 elements: Z accumulate + single quad-max key insert
__device__ __forceinline__ void proc4(float4 v, int j, float c1,
                                      float& z0, float& z1, float& z2, float& z3,
                                      u32 (&tv)[5]) {
    float e0 = ex2f(v.x * c1), e1 = ex2f(v.y * c1);
    float e2 = ex2f(v.z * c1), e3 = ex2f(v.w * c1);
    z0 += e0; z1 += e1; z2 += e2; z3 += e3;
    float m = fmaxf(fmaxf(e0, e1), fmaxf(e2, e3));
    u32 k = (__float_as_uint(m) & 0xFFFFE000u) | (u32)j;
    ins5(k, tv);
}

__global__ __launch_bounds__(TPB, 3)
void sampler_row_kernel(const float* __restrict__ logits,
                        const float* __restrict__ gumbel,
                        const float* __restrict__ temp_p,
                        const float* __restrict__ topp_p,
                        const int*   __restrict__ topk_p,
                        const float* __restrict__ thr_p,
                        float* __restrict__ out, int N)
{
    __shared__ float4 s_stage[DEPTH][SWORDS];   // 32 KB (mainloop only)
    __shared__ u32    s_hist[NBINS];            // 8 KB (reused for both tiers)
    __shared__ u32    s_g32[QCAP];              // gathered quad keys
    __shared__ u64    s_ckey[MCAP];             // compact candidate keys
    __shared__ float  s_cexp[MCAP];
    __shared__ float  s_cx[MCAP];
    __shared__ int    s_cidx[MCAP];
    __shared__ u32    s_t16[16];
    __shared__ u64    s_red64[16];
    __shared__ float  s_redf[16];
    __shared__ float  s_Z;
    __shared__ int    s_bin, s_gcnt, s_cnt2, s_last;

    const int tid  = threadIdx.x;
    const int row  = blockIdx.x;
    const int wid  = tid >> 5;
    const int lane = tid & 31;

    const float invT = 1.0f / (*temp_p);
    const float c1   = 1.44269504088896341f * invT;   // log2(e)/T
    const float topP = *topp_p;
    int Kw = *topk_p;
    Kw = max(1, min(Kw, 512));
    const int KQ = min(Kw, QCAP);          // quad-rank target
    const int Ke = min(Kw, 128);           // element-rank target (compact tier)

    const float* rowp = logits + (size_t)row * VOCAB;
    const float4* rp  = (const float4*)rowp;

    if (tid == 0) { s_gcnt = 0; s_cnt2 = 0; }
#pragma unroll
    for (int q = 0; q < NBINS / TPB; q++) s_hist[tid + q * TPB] = 0u;

    u32 tv[5];
#pragma unroll
    for (int q = 0; q < 5; q++) tv[q] = 0u;
    float z0 = 0.f, z1 = 0.f, z2 = 0.f, z3 = 0.f;

    const u32 sbase = (u32)__cvta_generic_to_shared(&s_stage[0][0]) + (u32)tid * 16u;

    // issue stage s (compile-time s after unroll -> immediate addresses)
#define ISSUE(s)                                                              \
    do {                                                                      \
        if ((s) < NSTAGES) {                                                  \
            const int _j = (s) * SWORDS;   /* + tid at runtime */             \
            u32 _dst = sbase + (u32)(((s) & (DEPTH - 1)) * SWORDS * 16);      \
            if ((s) < NSTAGES - 1) {                                          \
                asm volatile("cp.async.cg.shared.global [%0], [%1], 16;"      \
                             :: "r"(_dst), "l"(rp + _j + tid));               \
            } else {                                                          \
                if (_j + tid < VWORDS)                                        \
                    asm volatile("cp.async.cg.shared.global [%0], [%1], 16;"  \
                                 :: "r"(_dst), "l"(rp + _j + tid));           \
            }                                                                 \
        }                                                                     \
        asm volatile("cp.async.commit_group;");                               \
    } while (0)

    ISSUE(0); ISSUE(1); ISSUE(2); ISSUE(3);

#pragma unroll
    for (int s = 0; s < NSTAGES; s++) {
        asm volatile("cp.async.wait_group %0;" :: "n"(DEPTH - 1));
        int j = s * SWORDS + tid;
        if (s < NSTAGES - 1 || j < VWORDS) {
            float4 v = s_stage[s & (DEPTH - 1)][tid];
            proc4(v, j, c1, z0, z1, z2, z3, tv);
        }
        ISSUE(s + DEPTH);
    }
    asm volatile("cp.async.wait_group 0;");

    float zsum = (z0 + z1) + (z2 + z3);

    // ---- block-reduce Z ----
#pragma unroll
    for (int off = 16; off; off >>= 1)
        zsum += __shfl_down_sync(0xffffffffu, zsum, off);
    if (lane == 0) s_redf[wid] = zsum;
    __syncthreads();
    if (tid == 0) {
        float z = 0.0f;
        for (int w = 0; w < 16; w++) z += s_redf[w];
        s_Z = z;
    }

    // ---- tier 1: histogram of quad keys (top 11 bits) ----
#pragma unroll
    for (int q = 0; q < 5; q++)
        atomicAdd(&s_hist[tv[q] >> 21], 1u);
    __syncthreads();

    // suffix scan from highest bin; locate rank-KQ bin
    u32 c4[4]; u32 tsum = 0;
#pragma unroll
    for (int q = 0; q < 4; q++) {
        int bin = (NBINS - 1) - (tid * 4 + q);
        c4[q] = s_hist[bin];
        tsum += c4[q];
    }
    u32 incl = block_scan_u32(tsum, s_t16, tid);
    {
        u32 cum = incl - tsum;
#pragma unroll
        for (int q = 0; q < 4; q++) {
            if (cum < (u32)KQ && cum + c4[q] >= (u32)KQ)
                s_bin = (NBINS - 1) - (tid * 4 + q);
            cum += c4[q];
        }
    }
    __syncthreads();
    const int binSel = s_bin;

    // gather quad keys in bins >= binSel
#pragma unroll
    for (int q = 0; q < 5; q++) {
        u32 key = tv[q];
        if ((int)(key >> 21) >= binSel) {
            int pos = atomicAdd(&s_gcnt, 1);
            if (pos < QCAP) s_g32[pos] = key;
        }
    }
    __syncthreads();
    const int qcnt = min(s_gcnt, QCAP);
    const int gex  = qcnt * 4;           // expanded candidate count

    // ---- tier 2: expand quads in registers; element-level cutoff ----
    u64 myk = 0ull; float mye = 0.0f, myx = 0.0f; int myidx = 0; u32 mybits = 0;
    if (tid < gex) {
        u32 qk = s_g32[tid >> 2];
        myidx = ((int)(qk & 0x1FFFu)) * 4 + (tid & 3);
        myx = __ldg(rowp + myidx) * invT;
        mye = __expf(myx);
        mybits = f2s(myx);
        // tie-break: smaller idx -> larger low word -> higher rank
        myk = (((u64)mybits) << 32) | (u32)(VOCAB - myidx);
    }
    // clear histogram for reuse (tier-1 reads are complete)
#pragma unroll
    for (int q = 0; q < NBINS / TPB; q++) s_hist[tid + q * TPB] = 0u;
    __syncthreads();

    if (tid < gex) atomicAdd(&s_hist[mybits >> 21], 1u);
    __syncthreads();

    // suffix scan; locate element rank-Ke bin
    tsum = 0;
#pragma unroll
    for (int q = 0; q < 4; q++) {
        int bin = (NBINS - 1) - (tid * 4 + q);
        c4[q] = s_hist[bin];
        tsum += c4[q];
    }
    incl = block_scan_u32(tsum, s_t16, tid);
    {
        u32 cum = incl - tsum;
#pragma unroll
        for (int q = 0; q < 4; q++) {
            if (cum < (u32)Ke && cum + c4[q] >= (u32)Ke)
                s_bin = (NBINS - 1) - (tid * 4 + q);
            cum += c4[q];
        }
    }
    __syncthreads();
    const int binSel2 = s_bin;

    // gather compact candidates (rank provably < Ke + bin overshoot)
    if (tid < gex && (int)(mybits >> 21) >= binSel2) {
        int pos = atomicAdd(&s_cnt2, 1);
        if (pos < MCAP) {
            s_ckey[pos] = myk;
            s_cexp[pos] = mye;
            s_cx[pos]   = myx;
            s_cidx[pos] = myidx;
        }
    }
    __syncthreads();
    const int mcnt = min(s_cnt2, MCAP);

    // ---- all-pairs rank + prefix over compact set (~64 entries) ----
    float zc = 0.0f; u64 best = 0ull;
    if (tid < mcnt) {
        u64 mk = s_ckey[tid];
        int R = 0; float S = 0.0f;
        for (int j = 0; j < mcnt; j++) {
            u64 kj = s_ckey[j];
            bool gt = kj > mk;
            R += gt ? 1 : 0;
            S += gt ? s_cexp[j] : 0.0f;
        }
        if (R < Kw && S <= topP * s_Z) {
            zc = s_cexp[tid];
            float g = __ldg(&gumbel[(size_t)row * VOCAB + s_cidx[tid]]);
            best = (((u64)f2s(s_cx[tid] + g)) << 32) | (u32)tid;
        }
    }
#pragma unroll
    for (int off = 16; off; off >>= 1) {
        zc += __shfl_down_sync(0xffffffffu, zc, off);
        u64 o = __shfl_down_sync(0xffffffffu, best, off);
        if (o > best) best = o;
    }
    if (lane == 0) { s_redf[wid] = zc; s_red64[wid] = best; }
    __syncthreads();
    if (tid == 0) {
        float Zp = 0.0f; u64 b = 0ull;
        for (int w = 0; w < 16; w++) {
            Zp += s_redf[w];
            if (s_red64[w] > b) b = s_red64[w];
        }
        int sel = (int)(u32)b;
        float conf = s_cexp[sel] / Zp;
        out[row]         = conf;
        out[N + row]     = (float)s_cidx[sel];
        out[2 * N + row] = conf;

        __threadfence();
        int prev = atomicAdd(&g_done_ctr, 1);
        s_last = (prev == N - 1) ? 1 : 0;
    }
    __syncthreads();

    // ---- last block: cross-row finalize (accepted flags) ----
    if (s_last) {
        __threadfence();
        const float thr = *thr_p;
        u64 fb = 0ull; int anyl = 0;
        float cv[4];
#pragma unroll
        for (int q = 0; q < 4; q++) {
            int r = tid + q * TPB;
            float c = (r < N) ? out[r] : -1.0f;
            cv[q] = c;
            if (r < N) {
                if (c > thr) anyl = 1;
                u64 k = (((u64)f2s(c)) << 32) | (u32)(N - 1 - r);
                if (k > fb) fb = k;
            }
        }
#pragma unroll
        for (int off = 16; off; off >>= 1) {
            u64 o = __shfl_down_sync(0xffffffffu, fb, off);
            if (o > fb) fb = o;
        }
        int anyw = __any_sync(0xffffffffu, anyl);
        if (lane == 0) { s_red64[wid] = fb; s_t16[wid] = (u32)anyw; }
        __syncthreads();
        if (tid == 0) {
            u64 b = 0ull; u32 a = 0;
            for (int w = 0; w < 16; w++) {
                if (s_red64[w] > b) b = s_red64[w];
                a |= s_t16[w];
            }
            s_red64[0] = b;
            s_t16[0] = a;
            g_done_ctr = 0;
        }
        __syncthreads();
        const int argrow = N - 1 - (int)(u32)s_red64[0];
        const int anyh = (int)s_t16[0];
#pragma unroll
        for (int q = 0; q < 4; q++) {
            int r = tid + q * TPB;
            if (r < N)
                out[3 * N + r] = anyh ? ((cv[q] > thr) ? 1.0f : 0.0f)
                                      : ((r == argrow) ? 1.0f : 0.0f);
        }
    }
}

extern "C" void kernel_launch(void* const* d_in, const int* in_sizes, int n_in,
                              void* d_out, int out_size)
{
    const float* logits = (const float*)d_in[0];
    const float* gumbel = (const float*)d_in[1];
    const float* temp   = (const float*)d_in[2];
    const float* topp   = (const float*)d_in[3];
    const int*   topk   = (const int*)  d_in[4];
    const float* thr    = (const float*)d_in[5];

    int N = in_sizes[0] / VOCAB;
    float* out = (float*)d_out;

    sampler_row_kernel<<<N, TPB>>>(logits, gumbel, temp, topp, topk, thr, out, N);
}